// round 15
// baseline (speedup 1.0000x reference)
#include <cuda_runtime.h>
#include <cuda_fp16.h>
#include <cstdint>

// Problem constants
constexpr int D  = 1024;   // d_model
constexpr int S  = 2048;   // sequence length
constexpr int B  = 2;      // batch
constexpr int H  = 16;     // heads
constexpr int DH = 64;     // head dim
constexpr int M  = B * S;  // 4096 rows

// Scratch (device globals; no allocations allowed). 16B-aligned for cp.async.
__device__ __align__(256) __half g_x[M * D];
__device__ __align__(256) __half g_y[M * D];
__device__ __align__(256) __half g_wq[D * D];
__device__ __align__(256) __half g_wk[D * D];
__device__ __align__(256) __half g_wv[D * D];
__device__ __align__(256) __half g_q[M * D];     // head-split [B,H,S,DH]
__device__ __align__(256) __half g_k[M * D];
__device__ __align__(256) __half g_v[M * D];
__device__ __align__(256) __half g_wo[D * D];
__device__ __align__(256) __half g_att[M * D];   // [B,S,H*DH]

// Control block (cleared by one memset each call)
constexpr int FLQ   = 0;                 // work-queue counter
constexpr int FLMNZ = 1;                 // mask nonzero flag
constexpr int FLMCK = 2;                 // mask chunks checked (target 32)
constexpr int FLWC  = 3;                 // w cvt flags [proj*8+nt]   (24)
constexpr int FLYC  = 27;                // y cvt flags [m]           (32)
constexpr int FLXC  = 59;                // x cvt flags [m]           (32)
constexpr int FLQD  = 91;                // q_done [m*8+nt]           (256)
constexpr int FLKV  = 347;               // kv_cnt [b*8+nt] target 32 (16)
constexpr int FLATT = 363;               // att_cnt [m] target 16     (32)
constexpr int NFLAGS = 395;
__device__ int g_flags[NFLAGS];

// Queue layout (deps always at strictly lower indices -> deadlock-free)
constexpr int I_WCVT  = 0;      // 24 weight-convert items
constexpr int I_YCVT  = 24;     // 32 y-convert items
constexpr int I_XCVT  = 56;     // 32 x-convert items
constexpr int I_MCHK  = 88;     // 32 mask-check chunks
constexpr int I_QKV   = 120;    // 768 projection tiles
constexpr int I_FLASH = 888;    // 512 flash units
constexpr int I_O     = 1400;   // 256 o-proj tiles
constexpr int N_ITEMS = 1656;

// ---------------------------------------------------------------------------
// helpers
// ---------------------------------------------------------------------------
__device__ __forceinline__ void cp16(const void* smem_dst, const void* gmem_src) {
    unsigned d = (unsigned)__cvta_generic_to_shared(smem_dst);
    asm volatile("cp.async.cg.shared.global [%0], [%1], 16;" :: "r"(d), "l"(gmem_src));
}
__device__ __forceinline__ void cp_commit() { asm volatile("cp.async.commit_group;"); }
__device__ __forceinline__ void cp_wait0()  { asm volatile("cp.async.wait_group 0;"); }
__device__ __forceinline__ void cp_wait1()  { asm volatile("cp.async.wait_group 1;"); }

__device__ __forceinline__ uint32_t smem_u32(const void* p) {
    return (uint32_t)__cvta_generic_to_shared(p);
}

// D = A*B + D   (m16n8k16, f16 inputs, f32 accum)
__device__ __forceinline__ void mma16(float c[4],
                                      unsigned a0, unsigned a1, unsigned a2, unsigned a3,
                                      unsigned b0, unsigned b1) {
    asm volatile(
        "mma.sync.aligned.m16n8k16.row.col.f32.f16.f16.f32 "
        "{%0,%1,%2,%3},{%4,%5,%6,%7},{%8,%9},{%0,%1,%2,%3};"
        : "+f"(c[0]), "+f"(c[1]), "+f"(c[2]), "+f"(c[3])
        : "r"(a0), "r"(a1), "r"(a2), "r"(a3), "r"(b0), "r"(b1));
}

__device__ __forceinline__ void ldm_x4(unsigned r[4], uint32_t addr) {
    asm volatile("ldmatrix.sync.aligned.m8n8.x4.shared.b16 {%0,%1,%2,%3}, [%4];"
                 : "=r"(r[0]), "=r"(r[1]), "=r"(r[2]), "=r"(r[3]) : "r"(addr));
}
__device__ __forceinline__ void ldm_x4_trans(unsigned r[4], uint32_t addr) {
    asm volatile("ldmatrix.sync.aligned.m8n8.x4.trans.shared.b16 {%0,%1,%2,%3}, [%4];"
                 : "=r"(r[0]), "=r"(r[1]), "=r"(r[2]), "=r"(r[3]) : "r"(addr));
}

// ---------------------------------------------------------------------------
// Queue work: fp16 conversion of one 128x1024 block (32768 float4s)
// ---------------------------------------------------------------------------
__device__ __forceinline__
void cvt_block(const float4* __restrict__ src, uint2* __restrict__ dst, int base4)
{
    const float4* s = src + base4;
    uint2* d = dst + base4;
    for (int i = threadIdx.x; i < 32768; i += 256) {
        float4 v = s[i];
        __half2 h01 = __floats2half2_rn(v.x, v.y);
        __half2 h23 = __floats2half2_rn(v.z, v.w);
        uint2 u;
        u.x = *reinterpret_cast<unsigned*>(&h01);
        u.y = *reinterpret_cast<unsigned*>(&h23);
        d[i] = u;
    }
}

// ---------------------------------------------------------------------------
// GEMM tile: C[128x128] = A-panel @ W-panel^T, fp16 mma, cp.async 2-stage.
// 256 thr, 8 warps (4m x 2n), warp tile 32x64. Identical math to round 13/14.
// ---------------------------------------------------------------------------
constexpr int GSTRIDE = 72;                   // halfs per smem row (64 + 8 pad)
constexpr int GT = 128 * GSTRIDE;             // halfs per (matrix,stage)
constexpr int FUSED_SMEM = 4 * GT * 2;        // 73728 B (covers flash's 55296 too)

__device__ __forceinline__
void gemm_tile(const __half* __restrict__ A, const __half* __restrict__ W,
               void* __restrict__ Cout, int mode, int bx, int by, __half* smh)
{
    const int tid    = threadIdx.x;
    const int lane   = tid & 31;
    const int warp   = tid >> 5;
    const int warp_m = warp >> 1;    // 0..3
    const int warp_n = warp & 1;     // 0..1
    const int m0 = by * 128;
    const int n0 = bx * 128;
    const int lr = lane >> 2;
    const int lc = lane & 3;
    const int t8 = lane >> 3;
    const int rI = lane & 7;

    const int aOff = (warp_m * 32 + (t8 & 1) * 8 + rI) * GSTRIDE + (t8 >> 1) * 8;
    const int wOff = (warp_n * 64 + (t8 >> 1) * 8 + rI) * GSTRIDE + (t8 & 1) * 8;

    float acc[2][8][4];
#pragma unroll
    for (int i = 0; i < 2; i++)
#pragma unroll
        for (int j = 0; j < 8; j++)
#pragma unroll
            for (int t = 0; t < 4; t++) acc[i][j][t] = 0.f;

    auto load_stage = [&](int kc, __half* As, __half* Ws) {
        const __half* Ap = A + (size_t)m0 * D + kc * 64;
        const __half* Wp = W + (size_t)n0 * D + kc * 64;
#pragma unroll
        for (int t = 0; t < 4; t++) {
            int idx = tid + 256 * t;
            int row = idx >> 3;
            int seg = idx & 7;
            cp16(As + row * GSTRIDE + seg * 8, Ap + (size_t)row * D + seg * 8);
        }
#pragma unroll
        for (int t = 0; t < 4; t++) {
            int idx = tid + 256 * t;
            int row = idx >> 3;
            int seg = idx & 7;
            cp16(Ws + row * GSTRIDE + seg * 8, Wp + (size_t)row * D + seg * 8);
        }
    };

    load_stage(0, smh, smh + 2 * GT);
    cp_commit();

    for (int kt = 0; kt < 16; kt++) {
        const int s = kt & 1;
        if (kt < 15) {
            load_stage(kt + 1, smh + (s ^ 1) * GT, smh + 2 * GT + (s ^ 1) * GT);
            cp_commit();
            cp_wait1();
        } else {
            cp_wait0();
        }
        __syncthreads();

        const __half* As = smh + s * GT;
        const __half* Ws = smh + 2 * GT + s * GT;

#pragma unroll
        for (int ks = 0; ks < 4; ks++) {
            unsigned a[2][4];
            unsigned b[4][4];
#pragma unroll
            for (int mt = 0; mt < 2; mt++)
                ldm_x4(a[mt], smem_u32(As + aOff + mt * (16 * GSTRIDE) + ks * 16));
#pragma unroll
            for (int nt2 = 0; nt2 < 4; nt2++)
                ldm_x4(b[nt2], smem_u32(Ws + wOff + nt2 * (16 * GSTRIDE) + ks * 16));
#pragma unroll
            for (int nt2 = 0; nt2 < 4; nt2++) {
#pragma unroll
                for (int mt = 0; mt < 2; mt++) {
                    mma16(acc[mt][2 * nt2],     a[mt][0], a[mt][1], a[mt][2], a[mt][3], b[nt2][0], b[nt2][1]);
                    mma16(acc[mt][2 * nt2 + 1], a[mt][0], a[mt][1], a[mt][2], a[mt][3], b[nt2][2], b[nt2][3]);
                }
            }
        }
        __syncthreads();
    }

#pragma unroll
    for (int mt = 0; mt < 2; mt++) {
#pragma unroll
        for (int nt = 0; nt < 8; nt++) {
            int rA = m0 + warp_m * 32 + mt * 16 + lr;
            int cA = n0 + warp_n * 64 + nt * 8 + 2 * lc;
#pragma unroll
            for (int half_i = 0; half_i < 2; half_i++) {
                int m = rA + half_i * 8;
                float v0 = acc[mt][nt][half_i * 2 + 0];
                float v1 = acc[mt][nt][half_i * 2 + 1];
                if (mode == 0) {
                    *(float2*)((float*)Cout + (size_t)m * D + cA) = make_float2(v0, v1);
                } else {
                    int bb = m >> 11;
                    int ss = m & (S - 1);
                    int hh = cA >> 6;
                    int dh = cA & (DH - 1);
                    __half* dst = (__half*)Cout + (((size_t)(bb * H + hh) * S + ss) * DH + dh);
                    *(__half2*)dst = __floats2half2_rn(v0, v1);
                }
            }
        }
    }
}

// ---------------------------------------------------------------------------
// Flash unit: 128 q-rows of one (b,h). Identical math to round 13/14.
// ---------------------------------------------------------------------------
constexpr int KST = 64 * 72;     // halfs per K/V stage

__device__ __forceinline__
void flash_unit(const float* __restrict__ mask, int bb, int hh, int qx, __half* smh)
{
    __half* Ks2 = smh;
    __half* Vs2 = smh + 2 * KST;
    __half* Qs  = smh + 4 * KST;

    const int tid  = threadIdx.x;
    const int lane = tid & 31;
    const int warp = tid >> 5;
    const int lr = lane >> 2;
    const int lc = lane & 3;
    const int t8 = lane >> 3;
    const int rI = lane & 7;
    const int bh = bb * H + hh;
    const int qb = qx * 128;
    const int mnz = ((volatile int*)g_flags)[FLMNZ];

    const __half* qp    = g_q + ((size_t)bh * S + qb) * DH;
    const __half* kbase = g_k + (size_t)bh * S * DH;
    const __half* vbase = g_v + (size_t)bh * S * DH;

    const int kOff = ((t8 >> 1) * 8 + rI) * 72 + (t8 & 1) * 8;
    const int vOffRow = ((t8 & 1) * 8 + rI) * 72;
    const int vOffCol = (t8 >> 1) * 8;

    auto kv_load = [&](int kb, __half* Kd, __half* Vd) {
#pragma unroll
        for (int t = 0; t < 2; t++) {
            int idx = tid + 256 * t;
            int row = idx >> 3;
            int seg = idx & 7;
            cp16(Kd + row * 72 + seg * 8, kbase + (size_t)(kb + row) * DH + seg * 8);
        }
#pragma unroll
        for (int t = 0; t < 2; t++) {
            int idx = tid + 256 * t;
            int row = idx >> 3;
            int seg = idx & 7;
            cp16(Vd + row * 72 + seg * 8, vbase + (size_t)(kb + row) * DH + seg * 8);
        }
    };

#pragma unroll
    for (int t = 0; t < 4; t++) {
        int idx = tid + 256 * t;
        int row = idx >> 3;
        int seg = idx & 7;
        cp16(&Qs[row * 72 + seg * 8], qp + (size_t)row * DH + seg * 8);
    }
    cp_commit();
    kv_load(0, Ks2, Vs2);
    cp_commit();
    cp_wait1();
    __syncthreads();

    const int r0 = warp * 16 + lr;

    unsigned qf[4][4];
#pragma unroll
    for (int ks = 0; ks < 4; ks++) {
        const int kc = ks * 16 + 2 * lc;
        qf[ks][0] = *(const unsigned*)&Qs[r0 * 72 + kc];
        qf[ks][1] = *(const unsigned*)&Qs[(r0 + 8) * 72 + kc];
        qf[ks][2] = *(const unsigned*)&Qs[r0 * 72 + kc + 8];
        qf[ks][3] = *(const unsigned*)&Qs[(r0 + 8) * 72 + kc + 8];
    }

    float accO[8][4];
#pragma unroll
    for (int i = 0; i < 8; i++)
#pragma unroll
        for (int t = 0; t < 4; t++) accO[i][t] = 0.f;
    float rs0 = 0.f, rs1 = 0.f;

    for (int kt = 0; kt < S / 64; kt++) {
        const int s = kt & 1;
        if (kt < S / 64 - 1) {
            kv_load((kt + 1) * 64, Ks2 + (s ^ 1) * KST, Vs2 + (s ^ 1) * KST);
            cp_commit();
            cp_wait1();
        } else {
            cp_wait0();
        }
        __syncthreads();

        const __half* Ks = Ks2 + s * KST;
        const __half* Vs = Vs2 + s * KST;
        const int kb = kt * 64;

        float sAcc[8][4];
#pragma unroll
        for (int i = 0; i < 8; i++)
#pragma unroll
            for (int t = 0; t < 4; t++) sAcc[i][t] = 0.f;
#pragma unroll
        for (int ks = 0; ks < 4; ks++) {
            unsigned b[4][4];
#pragma unroll
            for (int nt2 = 0; nt2 < 4; nt2++)
                ldm_x4(b[nt2], smem_u32(Ks + kOff + nt2 * (16 * 72) + ks * 16));
#pragma unroll
            for (int nt2 = 0; nt2 < 4; nt2++) {
                mma16(sAcc[2 * nt2],     qf[ks][0], qf[ks][1], qf[ks][2], qf[ks][3], b[nt2][0], b[nt2][1]);
                mma16(sAcc[2 * nt2 + 1], qf[ks][0], qf[ks][1], qf[ks][2], qf[ks][3], b[nt2][2], b[nt2][3]);
            }
        }

        unsigned ph0[8], ph1[8];
#pragma unroll
        for (int nt = 0; nt < 8; nt++) {
            int col = nt * 8 + 2 * lc;
            float2 m0v = make_float2(0.f, 0.f);
            float2 m1v = make_float2(0.f, 0.f);
            if (mnz) {
                m0v = *(const float2*)(mask + (size_t)(qb + r0) * S + kb + col);
                m1v = *(const float2*)(mask + (size_t)(qb + r0 + 8) * S + kb + col);
            }
            float e00 = __expf(fmaf(sAcc[nt][0], 0.125f, m0v.x));
            float e01 = __expf(fmaf(sAcc[nt][1], 0.125f, m0v.y));
            float e10 = __expf(fmaf(sAcc[nt][2], 0.125f, m1v.x));
            float e11 = __expf(fmaf(sAcc[nt][3], 0.125f, m1v.y));
            rs0 += e00 + e01;
            rs1 += e10 + e11;
            __half2 h0 = __floats2half2_rn(e00, e01);
            __half2 h1 = __floats2half2_rn(e10, e11);
            ph0[nt] = *reinterpret_cast<unsigned*>(&h0);
            ph1[nt] = *reinterpret_cast<unsigned*>(&h1);
        }

#pragma unroll
        for (int ktc = 0; ktc < 4; ktc++) {
            unsigned a0 = ph0[2 * ktc];
            unsigned a1 = ph1[2 * ktc];
            unsigned a2 = ph0[2 * ktc + 1];
            unsigned a3 = ph1[2 * ktc + 1];
            unsigned v[4][4];
#pragma unroll
            for (int dtp = 0; dtp < 4; dtp++) {
                uint32_t addr = smem_u32(&Vs[ktc * (16 * 72) + vOffRow + dtp * 16 + vOffCol]);
                ldm_x4_trans(v[dtp], addr);
            }
#pragma unroll
            for (int dtp = 0; dtp < 4; dtp++) {
                mma16(accO[dtp * 2],     a0, a1, a2, a3, v[dtp][0], v[dtp][1]);
                mma16(accO[dtp * 2 + 1], a0, a1, a2, a3, v[dtp][2], v[dtp][3]);
            }
        }
        __syncthreads();
    }

    rs0 += __shfl_xor_sync(0xffffffffu, rs0, 1);
    rs0 += __shfl_xor_sync(0xffffffffu, rs0, 2);
    rs1 += __shfl_xor_sync(0xffffffffu, rs1, 1);
    rs1 += __shfl_xor_sync(0xffffffffu, rs1, 2);
    float inv0 = 1.f / (rs0 + 1e-10f);
    float inv1 = 1.f / (rs1 + 1e-10f);

    const int mrow0 = qb + r0;
#pragma unroll
    for (int dt = 0; dt < 8; dt++) {
        int col = hh * DH + dt * 8 + 2 * lc;
        __half* dst0 = g_att + ((size_t)(bb * S + mrow0)) * D + col;
        __half* dst1 = g_att + ((size_t)(bb * S + mrow0 + 8)) * D + col;
        *(__half2*)dst0 = __floats2half2_rn(accO[dt][0] * inv0, accO[dt][1] * inv0);
        *(__half2*)dst1 = __floats2half2_rn(accO[dt][2] * inv1, accO[dt][3] * inv1);
    }
}

// ---------------------------------------------------------------------------
// Fused persistent kernel: queue = [conversions | mask check | qkv | flash | o]
// with fine-grained dependency flags. Deps always at lower queue indices ->
// deadlock-free (all CTAs resident; earlier items always being executed).
// ---------------------------------------------------------------------------
__global__ __launch_bounds__(256, 2)
void fused_mha(const float* __restrict__ x, const float* __restrict__ y,
               const float* __restrict__ mask,
               const float* __restrict__ Wq, const float* __restrict__ Wk,
               const float* __restrict__ Wv, const float* __restrict__ Wo,
               float* __restrict__ out)
{
    extern __shared__ __half smh[];
    __shared__ int s_item;
    const int tid = threadIdx.x;
    volatile int* vf = (volatile int*)g_flags;

    for (;;) {
        if (tid == 0) s_item = atomicAdd(&g_flags[FLQ], 1);
        __syncthreads();
        const int item = s_item;
        __syncthreads();
        if (item >= N_ITEMS) return;

        if (item < I_YCVT) {
            // ---- weight convert: proj = i/8, row-block nt = i%8 ----
            const int i = item - I_WCVT;
            const int proj = i >> 3;
            const int nt   = i & 7;
            const float* src; __half* dst;
            if (proj == 0)      { src = (const float*)Wq; dst = g_wq; }
            else if (proj == 1) { src = (const float*)Wk; dst = g_wk; }
            else                { src = (const float*)Wv; dst = g_wv; }
            cvt_block((const float4*)src, (uint2*)dst, nt * 32768);
            __threadfence();
            __syncthreads();
            if (tid == 0) atomicExch(&g_flags[FLWC + i], 1);
        } else if (item < I_XCVT) {
            const int m = item - I_YCVT;
            cvt_block((const float4*)y, (uint2*)g_y, m * 32768);
            __threadfence();
            __syncthreads();
            if (tid == 0) atomicExch(&g_flags[FLYC + m], 1);
        } else if (item < I_MCHK) {
            const int m = item - I_XCVT;
            cvt_block((const float4*)x, (uint2*)g_x, m * 32768);
            __threadfence();
            __syncthreads();
            if (tid == 0) atomicExch(&g_flags[FLXC + m], 1);
        } else if (item < I_QKV) {
            // ---- mask check chunk ----
            const int c = item - I_MCHK;
            int found = 0;
            const float4* p = (const float4*)mask + c * 32768;
            for (int i = tid; i < 32768; i += 256) {
                float4 v = p[i];
                if (v.x != 0.f || v.y != 0.f || v.z != 0.f || v.w != 0.f) { found = 1; break; }
            }
            if (__syncthreads_or(found)) {
                if (tid == 0) atomicOr(&g_flags[FLMNZ], 1);
            }
            __threadfence();
            __syncthreads();
            if (tid == 0) atomicAdd(&g_flags[FLMCK], 1);
        } else if (item < I_FLASH) {
            // ---- projection tile: nt-major, then proj, then m ----
            const int j    = item - I_QKV;
            const int nt   = j / 96;
            const int rr   = j % 96;
            const int proj = rr / 32;
            const int m    = rr % 32;
            const __half *A, *W; __half* C;
            int adep, wdep;
            if (proj == 0)      { A = g_y; W = g_wq; C = g_q; adep = FLYC + m; wdep = FLWC + nt; }
            else if (proj == 1) { A = g_x; W = g_wk; C = g_k; adep = FLXC + m; wdep = FLWC + 8 + nt; }
            else                { A = g_x; W = g_wv; C = g_v; adep = FLXC + m; wdep = FLWC + 16 + nt; }
            if (tid == 0) {
                while (vf[adep] != 1 || vf[wdep] != 1) __nanosleep(64);
            }
            __syncthreads();
            __threadfence();
            gemm_tile(A, W, C, 1, nt, m, smh);
            __threadfence();
            __syncthreads();
            if (tid == 0) {
                if (proj == 0) atomicExch(&g_flags[FLQD + m * 8 + nt], 1);
                else           atomicAdd(&g_flags[FLKV + (m >> 4) * 8 + nt], 1);
            }
        } else if (item < I_O) {
            // ---- flash unit: h-major (deps = earliest qkv tiles) ----
            const int j  = item - I_FLASH;
            const int hh = j / 32;
            const int rr = j % 32;
            const int bb = rr / 16;
            const int qx = rr % 16;
            if (tid == 0) {
                const int qi = FLQD + (bb * 16 + qx) * 8 + (hh >> 1);
                const int ki = FLKV + bb * 8 + (hh >> 1);
                while (vf[qi] != 1 || vf[ki] < 32 || vf[FLMCK] < 32) __nanosleep(128);
            }
            __syncthreads();
            __threadfence();
            flash_unit(mask, bb, hh, qx, smh);
            __threadfence();
            __syncthreads();
            if (tid == 0) atomicAdd(&g_flags[FLATT + bb * 16 + qx], 1);
        } else {
            // ---- O-projection tile (needs full Wo: all 8 FLWC? Wo converted
            //      separately below via dedicated flag reuse — see wo items) ----
            const int j = item - I_O;
            const int m = j / 8;
            const int n = j % 8;
            if (tid == 0) {
                while (vf[FLATT + m] < 16) __nanosleep(128);
            }
            __syncthreads();
            __threadfence();
            gemm_tile(g_att, g_wo, out, 0, n, m, smh);
        }
        __syncthreads();
    }
}

// Wo is converted by a tiny standalone kernel BEFORE the fused launch (it is
// only needed by the o-phase at the end, but converting it up front costs ~2us
// and keeps the queue/dep logic simple).
__global__ void cvt_wo(const float4* __restrict__ wo)
{
    uint2* dst = (uint2*)g_wo;
    const int n4 = D * D / 4;
    for (int i = blockIdx.x * blockDim.x + threadIdx.x; i < n4;
         i += gridDim.x * blockDim.x) {
        float4 v = wo[i];
        __half2 h01 = __floats2half2_rn(v.x, v.y);
        __half2 h23 = __floats2half2_rn(v.z, v.w);
        uint2 u;
        u.x = *reinterpret_cast<unsigned*>(&h01);
        u.y = *reinterpret_cast<unsigned*>(&h23);
        dst[i] = u;
    }
}

// ---------------------------------------------------------------------------
extern "C" void kernel_launch(void* const* d_in, const int* in_sizes, int n_in,
                              void* d_out, int out_size)
{
    (void)in_sizes; (void)n_in; (void)out_size;
    const float* x    = (const float*)d_in[0];
    const float* y    = (const float*)d_in[1];
    const float* mask = (const float*)d_in[2];
    const float* Wq   = (const float*)d_in[3];
    const float* Wk   = (const float*)d_in[4];
    const float* Wv   = (const float*)d_in[5];
    const float* Wo   = (const float*)d_in[6];
    float* out = (float*)d_out;

    static bool attr_set = false;
    static int grid_blocks = 148;
    if (!attr_set) {
        cudaFuncSetAttribute(fused_mha, cudaFuncAttributeMaxDynamicSharedMemorySize,
                             FUSED_SMEM);
        int dev = 0, sm_count = 148, per_sm = 1;
        cudaGetDevice(&dev);
        cudaDeviceGetAttribute(&sm_count, cudaDevAttrMultiProcessorCount, dev);
        cudaOccupancyMaxActiveBlocksPerMultiprocessor(&per_sm, fused_mha, 256,
                                                      FUSED_SMEM);
        if (per_sm < 1) per_sm = 1;
        grid_blocks = sm_count * per_sm;
        attr_set = true;
    }

    // clear control block; convert Wo (needed only by the final o-phase)
    int* flag_ptr;
    cudaGetSymbolAddress((void**)&flag_ptr, g_flags);
    cudaMemsetAsync(flag_ptr, 0, sizeof(int) * NFLAGS);
    cvt_wo<<<256, 256>>>((const float4*)Wo);

    fused_mha<<<grid_blocks, 256, FUSED_SMEM>>>(x, y, mask, Wq, Wk, Wv, Wo, out);
}

// round 16
// speedup vs baseline: 1.0146x; 1.0146x over previous
#include <cuda_runtime.h>
#include <cuda_fp16.h>
#include <cstdint>

// Problem constants
constexpr int D  = 1024;   // d_model
constexpr int S  = 2048;   // sequence length
constexpr int B  = 2;      // batch
constexpr int H  = 16;     // heads
constexpr int DH = 64;     // head dim
constexpr int M  = B * S;  // 4096 rows

// Scratch (device globals; no allocations allowed). 16B-aligned for cp.async.
__device__ __align__(256) __half g_x[M * D];
__device__ __align__(256) __half g_y[M * D];
__device__ __align__(256) __half g_wq[D * D];
__device__ __align__(256) __half g_wk[D * D];
__device__ __align__(256) __half g_wv[D * D];
__device__ __align__(256) __half g_wo[D * D];
__device__ __align__(256) __half g_q[M * D];     // head-split [B,H,S,DH]
__device__ __align__(256) __half g_k[M * D];
__device__ __align__(256) __half g_v[M * D];
__device__ __align__(256) __half g_att[M * D];   // [B,S,H*DH]

// Control block (cleared by one memset each call)
constexpr int FLQ   = 0;     // work-queue counter
constexpr int FLMNZ = 1;     // mask nonzero flag
constexpr int FLMCK = 2;     // mask chunks checked (target 32)
constexpr int FLWC  = 3;     // w cvt counters [proj(4)*8+nt], target 2   (32)
constexpr int FLYC  = 35;    // y cvt counters [m], target 2              (32)
constexpr int FLXC  = 67;    // x cvt counters [m], target 2              (32)
constexpr int FLQD  = 99;    // q_done [m*8+nt]                           (256)
constexpr int FLKV  = 355;   // kv_cnt [b*8+nt], target 32                (16)
constexpr int FLATT = 371;   // att_cnt [m], target 16                    (32)
constexpr int NFLAGS = 403;
__device__ int g_flags[NFLAGS];

// Queue layout (deps always at strictly lower indices -> deadlock-free)
constexpr int I_WCVT  = 0;      // 64 weight half-block converts (4 proj x 16)
constexpr int I_YCVT  = 64;     // 64 y half-block converts
constexpr int I_XCVT  = 128;    // 64 x half-block converts
constexpr int I_MCHK  = 192;    // 32 mask-check chunks
constexpr int I_QKV   = 224;    // 768 projection tiles
constexpr int I_FLASH = 992;    // 512 flash units
constexpr int I_O     = 1504;   // 256 o-proj tiles
constexpr int N_ITEMS = 1760;

// ---------------------------------------------------------------------------
// helpers
// ---------------------------------------------------------------------------
__device__ __forceinline__ void cp16(const void* smem_dst, const void* gmem_src) {
    unsigned d = (unsigned)__cvta_generic_to_shared(smem_dst);
    asm volatile("cp.async.cg.shared.global [%0], [%1], 16;" :: "r"(d), "l"(gmem_src));
}
__device__ __forceinline__ void cp_commit() { asm volatile("cp.async.commit_group;"); }
__device__ __forceinline__ void cp_wait0()  { asm volatile("cp.async.wait_group 0;"); }
__device__ __forceinline__ void cp_wait1()  { asm volatile("cp.async.wait_group 1;"); }

__device__ __forceinline__ uint32_t smem_u32(const void* p) {
    return (uint32_t)__cvta_generic_to_shared(p);
}

// D = A*B + D   (m16n8k16, f16 inputs, f32 accum)
__device__ __forceinline__ void mma16(float c[4],
                                      unsigned a0, unsigned a1, unsigned a2, unsigned a3,
                                      unsigned b0, unsigned b1) {
    asm volatile(
        "mma.sync.aligned.m16n8k16.row.col.f32.f16.f16.f32 "
        "{%0,%1,%2,%3},{%4,%5,%6,%7},{%8,%9},{%0,%1,%2,%3};"
        : "+f"(c[0]), "+f"(c[1]), "+f"(c[2]), "+f"(c[3])
        : "r"(a0), "r"(a1), "r"(a2), "r"(a3), "r"(b0), "r"(b1));
}

__device__ __forceinline__ void ldm_x4(unsigned r[4], uint32_t addr) {
    asm volatile("ldmatrix.sync.aligned.m8n8.x4.shared.b16 {%0,%1,%2,%3}, [%4];"
                 : "=r"(r[0]), "=r"(r[1]), "=r"(r[2]), "=r"(r[3]) : "r"(addr));
}
__device__ __forceinline__ void ldm_x4_trans(unsigned r[4], uint32_t addr) {
    asm volatile("ldmatrix.sync.aligned.m8n8.x4.trans.shared.b16 {%0,%1,%2,%3}, [%4];"
                 : "=r"(r[0]), "=r"(r[1]), "=r"(r[2]), "=r"(r[3]) : "r"(addr));
}

// ---------------------------------------------------------------------------
// Queue work: fp16 conversion of one 64x1024 half-block (16384 float4s)
// ---------------------------------------------------------------------------
__device__ __forceinline__
void cvt_block64(const float4* __restrict__ src, uint2* __restrict__ dst, int base4)
{
    const float4* s = src + base4;
    uint2* d = dst + base4;
#pragma unroll 4
    for (int i = threadIdx.x; i < 16384; i += 256) {
        float4 v = s[i];
        __half2 h01 = __floats2half2_rn(v.x, v.y);
        __half2 h23 = __floats2half2_rn(v.z, v.w);
        uint2 u;
        u.x = *reinterpret_cast<unsigned*>(&h01);
        u.y = *reinterpret_cast<unsigned*>(&h23);
        d[i] = u;
    }
}

// ---------------------------------------------------------------------------
// GEMM tile: C[128x128] = A-panel @ W-panel^T, fp16 mma, cp.async 2-stage.
// 256 thr, 8 warps (4m x 2n), warp tile 32x64. Identical math to rounds 13-15.
// ---------------------------------------------------------------------------
constexpr int GSTRIDE = 72;                   // halfs per smem row (64 + 8 pad)
constexpr int GT = 128 * GSTRIDE;             // halfs per (matrix,stage)
constexpr int FUSED_SMEM = 4 * GT * 2;        // 73728 B (covers flash's 55296 too)

__device__ __forceinline__
void gemm_tile(const __half* __restrict__ A, const __half* __restrict__ W,
               void* __restrict__ Cout, int mode, int bx, int by, __half* smh)
{
    const int tid    = threadIdx.x;
    const int lane   = tid & 31;
    const int warp   = tid >> 5;
    const int warp_m = warp >> 1;    // 0..3
    const int warp_n = warp & 1;     // 0..1
    const int m0 = by * 128;
    const int n0 = bx * 128;
    const int lr = lane >> 2;
    const int lc = lane & 3;
    const int t8 = lane >> 3;
    const int rI = lane & 7;

    const int aOff = (warp_m * 32 + (t8 & 1) * 8 + rI) * GSTRIDE + (t8 >> 1) * 8;
    const int wOff = (warp_n * 64 + (t8 >> 1) * 8 + rI) * GSTRIDE + (t8 & 1) * 8;

    float acc[2][8][4];
#pragma unroll
    for (int i = 0; i < 2; i++)
#pragma unroll
        for (int j = 0; j < 8; j++)
#pragma unroll
            for (int t = 0; t < 4; t++) acc[i][j][t] = 0.f;

    auto load_stage = [&](int kc, __half* As, __half* Ws) {
        const __half* Ap = A + (size_t)m0 * D + kc * 64;
        const __half* Wp = W + (size_t)n0 * D + kc * 64;
#pragma unroll
        for (int t = 0; t < 4; t++) {
            int idx = tid + 256 * t;
            int row = idx >> 3;
            int seg = idx & 7;
            cp16(As + row * GSTRIDE + seg * 8, Ap + (size_t)row * D + seg * 8);
        }
#pragma unroll
        for (int t = 0; t < 4; t++) {
            int idx = tid + 256 * t;
            int row = idx >> 3;
            int seg = idx & 7;
            cp16(Ws + row * GSTRIDE + seg * 8, Wp + (size_t)row * D + seg * 8);
        }
    };

    load_stage(0, smh, smh + 2 * GT);
    cp_commit();

    for (int kt = 0; kt < 16; kt++) {
        const int s = kt & 1;
        if (kt < 15) {
            load_stage(kt + 1, smh + (s ^ 1) * GT, smh + 2 * GT + (s ^ 1) * GT);
            cp_commit();
            cp_wait1();
        } else {
            cp_wait0();
        }
        __syncthreads();

        const __half* As = smh + s * GT;
        const __half* Ws = smh + 2 * GT + s * GT;

#pragma unroll
        for (int ks = 0; ks < 4; ks++) {
            unsigned a[2][4];
            unsigned b[4][4];
#pragma unroll
            for (int mt = 0; mt < 2; mt++)
                ldm_x4(a[mt], smem_u32(As + aOff + mt * (16 * GSTRIDE) + ks * 16));
#pragma unroll
            for (int nt2 = 0; nt2 < 4; nt2++)
                ldm_x4(b[nt2], smem_u32(Ws + wOff + nt2 * (16 * GSTRIDE) + ks * 16));
#pragma unroll
            for (int nt2 = 0; nt2 < 4; nt2++) {
#pragma unroll
                for (int mt = 0; mt < 2; mt++) {
                    mma16(acc[mt][2 * nt2],     a[mt][0], a[mt][1], a[mt][2], a[mt][3], b[nt2][0], b[nt2][1]);
                    mma16(acc[mt][2 * nt2 + 1], a[mt][0], a[mt][1], a[mt][2], a[mt][3], b[nt2][2], b[nt2][3]);
                }
            }
        }
        __syncthreads();
    }

#pragma unroll
    for (int mt = 0; mt < 2; mt++) {
#pragma unroll
        for (int nt = 0; nt < 8; nt++) {
            int rA = m0 + warp_m * 32 + mt * 16 + lr;
            int cA = n0 + warp_n * 64 + nt * 8 + 2 * lc;
#pragma unroll
            for (int half_i = 0; half_i < 2; half_i++) {
                int m = rA + half_i * 8;
                float v0 = acc[mt][nt][half_i * 2 + 0];
                float v1 = acc[mt][nt][half_i * 2 + 1];
                if (mode == 0) {
                    *(float2*)((float*)Cout + (size_t)m * D + cA) = make_float2(v0, v1);
                } else {
                    int bb = m >> 11;
                    int ss = m & (S - 1);
                    int hh = cA >> 6;
                    int dh = cA & (DH - 1);
                    __half* dst = (__half*)Cout + (((size_t)(bb * H + hh) * S + ss) * DH + dh);
                    *(__half2*)dst = __floats2half2_rn(v0, v1);
                }
            }
        }
    }
}

// ---------------------------------------------------------------------------
// Flash unit: 128 q-rows of one (b,h). Identical math to rounds 13-15.
// ---------------------------------------------------------------------------
constexpr int KST = 64 * 72;     // halfs per K/V stage

__device__ __forceinline__
void flash_unit(const float* __restrict__ mask, int bb, int hh, int qx, __half* smh)
{
    __half* Ks2 = smh;
    __half* Vs2 = smh + 2 * KST;
    __half* Qs  = smh + 4 * KST;

    const int tid  = threadIdx.x;
    const int lane = tid & 31;
    const int warp = tid >> 5;
    const int lr = lane >> 2;
    const int lc = lane & 3;
    const int t8 = lane >> 3;
    const int rI = lane & 7;
    const int bh = bb * H + hh;
    const int qb = qx * 128;
    const int mnz = ((volatile int*)g_flags)[FLMNZ];

    const __half* qp    = g_q + ((size_t)bh * S + qb) * DH;
    const __half* kbase = g_k + (size_t)bh * S * DH;
    const __half* vbase = g_v + (size_t)bh * S * DH;

    const int kOff = ((t8 >> 1) * 8 + rI) * 72 + (t8 & 1) * 8;
    const int vOffRow = ((t8 & 1) * 8 + rI) * 72;
    const int vOffCol = (t8 >> 1) * 8;

    auto kv_load = [&](int kb, __half* Kd, __half* Vd) {
#pragma unroll
        for (int t = 0; t < 2; t++) {
            int idx = tid + 256 * t;
            int row = idx >> 3;
            int seg = idx & 7;
            cp16(Kd + row * 72 + seg * 8, kbase + (size_t)(kb + row) * DH + seg * 8);
        }
#pragma unroll
        for (int t = 0; t < 2; t++) {
            int idx = tid + 256 * t;
            int row = idx >> 3;
            int seg = idx & 7;
            cp16(Vd + row * 72 + seg * 8, vbase + (size_t)(kb + row) * DH + seg * 8);
        }
    };

#pragma unroll
    for (int t = 0; t < 4; t++) {
        int idx = tid + 256 * t;
        int row = idx >> 3;
        int seg = idx & 7;
        cp16(&Qs[row * 72 + seg * 8], qp + (size_t)row * DH + seg * 8);
    }
    cp_commit();
    kv_load(0, Ks2, Vs2);
    cp_commit();
    cp_wait1();
    __syncthreads();

    const int r0 = warp * 16 + lr;

    unsigned qf[4][4];
#pragma unroll
    for (int ks = 0; ks < 4; ks++) {
        const int kc = ks * 16 + 2 * lc;
        qf[ks][0] = *(const unsigned*)&Qs[r0 * 72 + kc];
        qf[ks][1] = *(const unsigned*)&Qs[(r0 + 8) * 72 + kc];
        qf[ks][2] = *(const unsigned*)&Qs[r0 * 72 + kc + 8];
        qf[ks][3] = *(const unsigned*)&Qs[(r0 + 8) * 72 + kc + 8];
    }

    float accO[8][4];
#pragma unroll
    for (int i = 0; i < 8; i++)
#pragma unroll
        for (int t = 0; t < 4; t++) accO[i][t] = 0.f;
    float rs0 = 0.f, rs1 = 0.f;

    for (int kt = 0; kt < S / 64; kt++) {
        const int s = kt & 1;
        if (kt < S / 64 - 1) {
            kv_load((kt + 1) * 64, Ks2 + (s ^ 1) * KST, Vs2 + (s ^ 1) * KST);
            cp_commit();
            cp_wait1();
        } else {
            cp_wait0();
        }
        __syncthreads();

        const __half* Ks = Ks2 + s * KST;
        const __half* Vs = Vs2 + s * KST;
        const int kb = kt * 64;

        float sAcc[8][4];
#pragma unroll
        for (int i = 0; i < 8; i++)
#pragma unroll
            for (int t = 0; t < 4; t++) sAcc[i][t] = 0.f;
#pragma unroll
        for (int ks = 0; ks < 4; ks++) {
            unsigned b[4][4];
#pragma unroll
            for (int nt2 = 0; nt2 < 4; nt2++)
                ldm_x4(b[nt2], smem_u32(Ks + kOff + nt2 * (16 * 72) + ks * 16));
#pragma unroll
            for (int nt2 = 0; nt2 < 4; nt2++) {
                mma16(sAcc[2 * nt2],     qf[ks][0], qf[ks][1], qf[ks][2], qf[ks][3], b[nt2][0], b[nt2][1]);
                mma16(sAcc[2 * nt2 + 1], qf[ks][0], qf[ks][1], qf[ks][2], qf[ks][3], b[nt2][2], b[nt2][3]);
            }
        }

        unsigned ph0[8], ph1[8];
#pragma unroll
        for (int nt = 0; nt < 8; nt++) {
            int col = nt * 8 + 2 * lc;
            float2 m0v = make_float2(0.f, 0.f);
            float2 m1v = make_float2(0.f, 0.f);
            if (mnz) {
                m0v = *(const float2*)(mask + (size_t)(qb + r0) * S + kb + col);
                m1v = *(const float2*)(mask + (size_t)(qb + r0 + 8) * S + kb + col);
            }
            float e00 = __expf(fmaf(sAcc[nt][0], 0.125f, m0v.x));
            float e01 = __expf(fmaf(sAcc[nt][1], 0.125f, m0v.y));
            float e10 = __expf(fmaf(sAcc[nt][2], 0.125f, m1v.x));
            float e11 = __expf(fmaf(sAcc[nt][3], 0.125f, m1v.y));
            rs0 += e00 + e01;
            rs1 += e10 + e11;
            __half2 h0 = __floats2half2_rn(e00, e01);
            __half2 h1 = __floats2half2_rn(e10, e11);
            ph0[nt] = *reinterpret_cast<unsigned*>(&h0);
            ph1[nt] = *reinterpret_cast<unsigned*>(&h1);
        }

#pragma unroll
        for (int ktc = 0; ktc < 4; ktc++) {
            unsigned a0 = ph0[2 * ktc];
            unsigned a1 = ph1[2 * ktc];
            unsigned a2 = ph0[2 * ktc + 1];
            unsigned a3 = ph1[2 * ktc + 1];
            unsigned v[4][4];
#pragma unroll
            for (int dtp = 0; dtp < 4; dtp++) {
                uint32_t addr = smem_u32(&Vs[ktc * (16 * 72) + vOffRow + dtp * 16 + vOffCol]);
                ldm_x4_trans(v[dtp], addr);
            }
#pragma unroll
            for (int dtp = 0; dtp < 4; dtp++) {
                mma16(accO[dtp * 2],     a0, a1, a2, a3, v[dtp][0], v[dtp][1]);
                mma16(accO[dtp * 2 + 1], a0, a1, a2, a3, v[dtp][2], v[dtp][3]);
            }
        }
        __syncthreads();
    }

    rs0 += __shfl_xor_sync(0xffffffffu, rs0, 1);
    rs0 += __shfl_xor_sync(0xffffffffu, rs0, 2);
    rs1 += __shfl_xor_sync(0xffffffffu, rs1, 1);
    rs1 += __shfl_xor_sync(0xffffffffu, rs1, 2);
    float inv0 = 1.f / (rs0 + 1e-10f);
    float inv1 = 1.f / (rs1 + 1e-10f);

    const int mrow0 = qb + r0;
#pragma unroll
    for (int dt = 0; dt < 8; dt++) {
        int col = hh * DH + dt * 8 + 2 * lc;
        __half* dst0 = g_att + ((size_t)(bb * S + mrow0)) * D + col;
        __half* dst1 = g_att + ((size_t)(bb * S + mrow0 + 8)) * D + col;
        *(__half2*)dst0 = __floats2half2_rn(accO[dt][0] * inv0, accO[dt][1] * inv0);
        *(__half2*)dst1 = __floats2half2_rn(accO[dt][2] * inv1, accO[dt][3] * inv1);
    }
}

// ---------------------------------------------------------------------------
// Fused persistent kernel: queue = [cvt (fine) | mask | qkv | flash | o]
// Deps always at lower queue indices -> deadlock-free.
// ---------------------------------------------------------------------------
__global__ __launch_bounds__(256, 2)
void fused_mha(const float* __restrict__ x, const float* __restrict__ y,
               const float* __restrict__ mask,
               const float* __restrict__ Wq, const float* __restrict__ Wk,
               const float* __restrict__ Wv, const float* __restrict__ Wo,
               float* __restrict__ out)
{
    extern __shared__ __half smh[];
    __shared__ int s_item;
    const int tid = threadIdx.x;
    volatile int* vf = (volatile int*)g_flags;

    for (;;) {
        if (tid == 0) s_item = atomicAdd(&g_flags[FLQ], 1);
        __syncthreads();
        const int item = s_item;
        __syncthreads();
        if (item >= N_ITEMS) return;

        if (item < I_YCVT) {
            // ---- weight half-block convert: proj = i/16, half = i%16 ----
            const int i = item - I_WCVT;
            const int proj = i >> 4;
            const int half = i & 15;
            const float* src; __half* dst;
            if (proj == 0)      { src = (const float*)Wq; dst = g_wq; }
            else if (proj == 1) { src = (const float*)Wk; dst = g_wk; }
            else if (proj == 2) { src = (const float*)Wv; dst = g_wv; }
            else                { src = (const float*)Wo; dst = g_wo; }
            cvt_block64((const float4*)src, (uint2*)dst, half * 16384);
            __threadfence();
            __syncthreads();
            if (tid == 0) atomicAdd(&g_flags[FLWC + proj * 8 + (half >> 1)], 1);
        } else if (item < I_XCVT) {
            const int i = item - I_YCVT;          // 0..63 (half-block of y)
            cvt_block64((const float4*)y, (uint2*)g_y, i * 16384);
            __threadfence();
            __syncthreads();
            if (tid == 0) atomicAdd(&g_flags[FLYC + (i >> 1)], 1);
        } else if (item < I_MCHK) {
            const int i = item - I_XCVT;          // 0..63 (half-block of x)
            cvt_block64((const float4*)x, (uint2*)g_x, i * 16384);
            __threadfence();
            __syncthreads();
            if (tid == 0) atomicAdd(&g_flags[FLXC + (i >> 1)], 1);
        } else if (item < I_QKV) {
            // ---- mask check chunk ----
            const int c = item - I_MCHK;
            int found = 0;
            const float4* p = (const float4*)mask + c * 32768;
            for (int i = tid; i < 32768; i += 256) {
                float4 v = p[i];
                if (v.x != 0.f || v.y != 0.f || v.z != 0.f || v.w != 0.f) { found = 1; break; }
            }
            if (__syncthreads_or(found)) {
                if (tid == 0) atomicOr(&g_flags[FLMNZ], 1);
            }
            __threadfence();
            __syncthreads();
            if (tid == 0) atomicAdd(&g_flags[FLMCK], 1);
        } else if (item < I_FLASH) {
            // ---- projection tile: nt-major, then proj, then m ----
            const int j    = item - I_QKV;
            const int nt   = j / 96;
            const int rr   = j % 96;
            const int proj = rr / 32;
            const int m    = rr % 32;
            const __half *A, *W; __half* C;
            int adep, wdep;
            if (proj == 0)      { A = g_y; W = g_wq; C = g_q; adep = FLYC + m; wdep = FLWC + nt; }
            else if (proj == 1) { A = g_x; W = g_wk; C = g_k; adep = FLXC + m; wdep = FLWC + 8 + nt; }
            else                { A = g_x; W = g_wv; C = g_v; adep = FLXC + m; wdep = FLWC + 16 + nt; }
            if (tid == 0) {
                while (vf[adep] < 2 || vf[wdep] < 2) __nanosleep(64);
            }
            __syncthreads();
            __threadfence();
            gemm_tile(A, W, C, 1, nt, m, smh);
            __threadfence();
            __syncthreads();
            if (tid == 0) {
                if (proj == 0) atomicExch(&g_flags[FLQD + m * 8 + nt], 1);
                else           atomicAdd(&g_flags[FLKV + (m >> 4) * 8 + nt], 1);
            }
        } else if (item < I_O) {
            // ---- flash unit: h-major (deps = earliest qkv tiles) ----
            const int j  = item - I_FLASH;
            const int hh = j / 32;
            const int rr = j % 32;
            const int bb = rr / 16;
            const int qx = rr % 16;
            if (tid == 0) {
                const int qi = FLQD + (bb * 16 + qx) * 8 + (hh >> 1);
                const int ki = FLKV + bb * 8 + (hh >> 1);
                while (vf[qi] != 1 || vf[ki] < 32 || vf[FLMCK] < 32) __nanosleep(128);
            }
            __syncthreads();
            __threadfence();
            flash_unit(mask, bb, hh, qx, smh);
            __threadfence();
            __syncthreads();
            if (tid == 0) atomicAdd(&g_flags[FLATT + bb * 16 + qx], 1);
        } else {
            // ---- O-projection tile: needs att row-block m and Wo n-block ----
            const int j = item - I_O;
            const int m = j / 8;
            const int n = j % 8;
            if (tid == 0) {
                while (vf[FLATT + m] < 16 || vf[FLWC + 24 + n] < 2) __nanosleep(128);
            }
            __syncthreads();
            __threadfence();
            gemm_tile(g_att, g_wo, out, 0, n, m, smh);
        }
        __syncthreads();
    }
}

// ---------------------------------------------------------------------------
extern "C" void kernel_launch(void* const* d_in, const int* in_sizes, int n_in,
                              void* d_out, int out_size)
{
    (void)in_sizes; (void)n_in; (void)out_size;
    const float* x    = (const float*)d_in[0];
    const float* y    = (const float*)d_in[1];
    const float* mask = (const float*)d_in[2];
    const float* Wq   = (const float*)d_in[3];
    const float* Wk   = (const float*)d_in[4];
    const float* Wv   = (const float*)d_in[5];
    const float* Wo   = (const float*)d_in[6];
    float* out = (float*)d_out;

    static bool attr_set = false;
    static int grid_blocks = 148;
    if (!attr_set) {
        cudaFuncSetAttribute(fused_mha, cudaFuncAttributeMaxDynamicSharedMemorySize,
                             FUSED_SMEM);
        int dev = 0, sm_count = 148, per_sm = 1;
        cudaGetDevice(&dev);
        cudaDeviceGetAttribute(&sm_count, cudaDevAttrMultiProcessorCount, dev);
        cudaOccupancyMaxActiveBlocksPerMultiprocessor(&per_sm, fused_mha, 256,
                                                      FUSED_SMEM);
        if (per_sm < 1) per_sm = 1;
        grid_blocks = sm_count * per_sm;
        attr_set = true;
    }

    int* flag_ptr;
    cudaGetSymbolAddress((void**)&flag_ptr, g_flags);
    cudaMemsetAsync(flag_ptr, 0, sizeof(int) * NFLAGS);

    fused_mha<<<grid_blocks, 256, FUSED_SMEM>>>(x, y, mask, Wq, Wk, Wv, Wo, out);
}